// round 4
// baseline (speedup 1.0000x reference)
#include <cuda_runtime.h>
#include <math.h>

#define NMAX 50000
#define EMAX 640000

// Scratch (static device arrays: allocation-free per harness rules)
__device__ float g_deg[NMAX];
__device__ float g_dinv[NMAX];
__device__ float g_norm[EMAX];
__device__ float g_xw[NMAX * 128];
__device__ float g_agg1[NMAX * 128];
__device__ float g_hw[NMAX * 40];

// ---------------------------------------------------------------------------
// degree / normalization  (edge_index is INT32 on device: jax x64 is disabled)
// ---------------------------------------------------------------------------
__global__ void k_deg_init(int n) {
    int i = blockIdx.x * blockDim.x + threadIdx.x;
    if (i < n) g_deg[i] = 1.0f;  // self-loop contributes 1
}

__global__ void k_deg_edges(const int* __restrict__ ei, int E) {
    int e = blockIdx.x * blockDim.x + threadIdx.x;
    if (e < E) atomicAdd(&g_deg[ei[E + e]], 1.0f);
}

__global__ void k_dinv(int n) {
    int i = blockIdx.x * blockDim.x + threadIdx.x;
    if (i < n) g_dinv[i] = rsqrtf(g_deg[i]);
}

__global__ void k_norm(const int* __restrict__ ei, int E) {
    int e = blockIdx.x * blockDim.x + threadIdx.x;
    if (e < E) g_norm[e] = g_dinv[ei[e]] * g_dinv[ei[E + e]];
}

// ---------------------------------------------------------------------------
// GEMM1: xw = x @ W1     [N,128] @ [128,128]
// Block: 256 threads, 64 rows x 128 cols, two K=64 smem tiles (48KB static).
// ---------------------------------------------------------------------------
__global__ void k_gemm1(const float* __restrict__ x, const float* __restrict__ W,
                        int nrows) {
    __shared__ float4 sW[64 * 32];  // 64 k-rows x 128 cols  (32KB)
    __shared__ float4 sX[64 * 16];  // 64 rows  x 64 cols    (16KB)
    int tid = threadIdx.x;
    int rowBase = blockIdx.x * 64;
    int cg = tid & 31;   // column group: cols [cg*4, cg*4+4)
    int rg = tid >> 5;   // row group: rows [rg*8, rg*8+8)

    float4 acc[8];
#pragma unroll
    for (int r = 0; r < 8; r++) acc[r] = make_float4(0.f, 0.f, 0.f, 0.f);

    const float4* X4 = (const float4*)x;
    const float4* W4 = (const float4*)W;

    for (int kt = 0; kt < 2; kt++) {
        __syncthreads();
        for (int i = tid; i < 64 * 32; i += 256) {
            int kr = i >> 5, c = i & 31;
            sW[i] = W4[(kt * 64 + kr) * 32 + c];
        }
        for (int i = tid; i < 64 * 16; i += 256) {
            int r = i >> 4, c = i & 15;
            int grow = rowBase + r;
            sX[i] = (grow < nrows) ? X4[grow * 32 + kt * 16 + c]
                                   : make_float4(0.f, 0.f, 0.f, 0.f);
        }
        __syncthreads();
#pragma unroll
        for (int k4 = 0; k4 < 16; k4++) {
            float4 w0 = sW[(k4 * 4 + 0) * 32 + cg];
            float4 w1 = sW[(k4 * 4 + 1) * 32 + cg];
            float4 w2 = sW[(k4 * 4 + 2) * 32 + cg];
            float4 w3 = sW[(k4 * 4 + 3) * 32 + cg];
#pragma unroll
            for (int r = 0; r < 8; r++) {
                float4 xv = sX[(rg * 8 + r) * 16 + k4];
                acc[r].x += xv.x * w0.x + xv.y * w1.x + xv.z * w2.x + xv.w * w3.x;
                acc[r].y += xv.x * w0.y + xv.y * w1.y + xv.z * w2.y + xv.w * w3.y;
                acc[r].z += xv.x * w0.z + xv.y * w1.z + xv.z * w2.z + xv.w * w3.z;
                acc[r].w += xv.x * w0.w + xv.y * w1.w + xv.z * w2.w + xv.w * w3.w;
            }
        }
    }
    float4* xw4 = (float4*)g_xw;
#pragma unroll
    for (int r = 0; r < 8; r++) {
        int grow = rowBase + rg * 8 + r;
        if (grow < nrows) xw4[grow * 32 + cg] = acc[r];
    }
}

// ---------------------------------------------------------------------------
// self-loop init layer 1: agg1 = xw * dinv^2  (full overwrite, no zeroing)
// ---------------------------------------------------------------------------
__global__ void k_self1(int n) {
    int t = blockIdx.x * blockDim.x + threadIdx.x;
    if (t >= n * 32) return;
    int row = t >> 5;
    float d = g_dinv[row];
    float s = d * d;
    float4 v = ((const float4*)g_xw)[t];
    ((float4*)g_agg1)[t] = make_float4(v.x * s, v.y * s, v.z * s, v.w * s);
}

// ---------------------------------------------------------------------------
// edge scatter layer 1: one warp per edge, lane = float4 chunk (32x16B = row)
// 4 scalar atomicAdds per lane -> RED.E.ADD.F32 (no return).
// ---------------------------------------------------------------------------
__global__ void k_scat1(const int* __restrict__ ei, int E) {
    int t = blockIdx.x * blockDim.x + threadIdx.x;
    int e = t >> 5;
    if (e >= E) return;
    int lane = t & 31;
    int src = ei[e];
    int dst = ei[E + e];
    float nrm = g_norm[e];
    float4 v = ((const float4*)g_xw)[src * 32 + lane];
    float* p = g_agg1 + dst * 128 + lane * 4;
    atomicAdd(p + 0, v.x * nrm);
    atomicAdd(p + 1, v.y * nrm);
    atomicAdd(p + 2, v.z * nrm);
    atomicAdd(p + 3, v.w * nrm);
}

// ---------------------------------------------------------------------------
// GEMM2: hw = relu(agg1 + b1) @ W2   [N,128] @ [128,40]
// ---------------------------------------------------------------------------
__global__ void k_gemm2(const float* __restrict__ b1, const float* __restrict__ W2,
                        int nrows) {
    __shared__ float2 sW[128 * 20];  // 20KB
    __shared__ float sH[48 * 128];   // 24KB
    int tid = threadIdx.x;
    int rowBase = blockIdx.x * 48;

    const float2* W2v = (const float2*)W2;
    for (int i = tid; i < 128 * 20; i += 256) sW[i] = W2v[i];

    const float4* A4 = (const float4*)g_agg1;
    const float4* B14 = (const float4*)b1;
    float4* sH4 = (float4*)sH;
    for (int i = tid; i < 48 * 32; i += 256) {
        int r = i >> 5, c = i & 31;
        int grow = rowBase + r;
        float4 v = (grow < nrows) ? A4[grow * 32 + c] : make_float4(0.f, 0.f, 0.f, 0.f);
        float4 b = B14[c];
        v.x = fmaxf(v.x + b.x, 0.f);
        v.y = fmaxf(v.y + b.y, 0.f);
        v.z = fmaxf(v.z + b.z, 0.f);
        v.w = fmaxf(v.w + b.w, 0.f);
        sH4[i] = v;
    }
    __syncthreads();

    int w = tid >> 5, lane = tid & 31;
    bool act = lane < 20;
    float2 acc[6];
#pragma unroll
    for (int r = 0; r < 6; r++) acc[r] = make_float2(0.f, 0.f);

#pragma unroll 4
    for (int k = 0; k < 128; k++) {
        float2 wv = act ? sW[k * 20 + lane] : make_float2(0.f, 0.f);
#pragma unroll
        for (int r = 0; r < 6; r++) {
            float hv = sH[(w * 6 + r) * 128 + k];
            acc[r].x += hv * wv.x;
            acc[r].y += hv * wv.y;
        }
    }

    if (act) {
        float2* hw2 = (float2*)g_hw;
#pragma unroll
        for (int r = 0; r < 6; r++) {
            int grow = rowBase + w * 6 + r;
            if (grow < nrows) hw2[grow * 20 + lane] = acc[r];
        }
    }
}

// ---------------------------------------------------------------------------
// self-loop init layer 2: out = hw * dinv^2 + b2 (initializes poisoned d_out)
// ---------------------------------------------------------------------------
__global__ void k_self2(const float* __restrict__ b2, float* __restrict__ out, int n) {
    int t = blockIdx.x * blockDim.x + threadIdx.x;
    if (t >= n * 10) return;
    int row = t / 10;
    int j = t - row * 10;
    float d = g_dinv[row];
    float s = d * d;
    float4 v = ((const float4*)g_hw)[t];
    float4 b = ((const float4*)b2)[j];
    ((float4*)out)[t] = make_float4(v.x * s + b.x, v.y * s + b.y,
                                    v.z * s + b.z, v.w * s + b.w);
}

// ---------------------------------------------------------------------------
// edge scatter layer 2: one thread per (edge, float4-chunk), 10 chunks/edge
// ---------------------------------------------------------------------------
__global__ void k_scat2(const int* __restrict__ ei, float* __restrict__ out,
                        int E) {
    int t = blockIdx.x * blockDim.x + threadIdx.x;
    if (t >= E * 10) return;
    int e = t / 10;
    int j = t - e * 10;
    int src = ei[e];
    int dst = ei[E + e];
    float nrm = g_norm[e];
    float4 v = ((const float4*)g_hw)[src * 10 + j];
    float* p = out + dst * 40 + j * 4;
    atomicAdd(p + 0, v.x * nrm);
    atomicAdd(p + 1, v.y * nrm);
    atomicAdd(p + 2, v.z * nrm);
    atomicAdd(p + 3, v.w * nrm);
}

// ---------------------------------------------------------------------------
extern "C" void kernel_launch(void* const* d_in, const int* in_sizes, int n_in,
                              void* d_out, int out_size) {
    const float* x = (const float*)d_in[0];
    const int* ei = (const int*)d_in[1];   // int32! (jax x64 disabled)
    const float* W1 = (const float*)d_in[2];
    const float* b1 = (const float*)d_in[3];
    const float* W2 = (const float*)d_in[4];
    const float* b2 = (const float*)d_in[5];
    float* out = (float*)d_out;

    int N = in_sizes[0] / 128;  // 50000
    int E = in_sizes[1] / 2;    // 640000

    k_deg_init<<<(N + 255) / 256, 256>>>(N);
    k_deg_edges<<<(E + 255) / 256, 256>>>(ei, E);
    k_dinv<<<(N + 255) / 256, 256>>>(N);
    k_norm<<<(E + 255) / 256, 256>>>(ei, E);

    k_gemm1<<<(N + 63) / 64, 256>>>(x, W1, N);
    k_self1<<<(N * 32 + 255) / 256, 256>>>(N);
    k_scat1<<<(E * 32 + 255) / 256, 256>>>(ei, E);

    k_gemm2<<<(N + 47) / 48, 256>>>(b1, W2, N);
    k_self2<<<(N * 10 + 255) / 256, 256>>>(b2, out, N);
    k_scat2<<<(E * 10 + 255) / 256, 256>>>(ei, out, E);
}

// round 5
// speedup vs baseline: 2.2955x; 2.2955x over previous
#include <cuda_runtime.h>
#include <math.h>

#define NMAX 50000
#define EMAX 640000
#define NBLK 256           // scan block size
#define NSCANB ((NMAX + NBLK - 1) / NBLK)   // 196

// Scratch (static device arrays: allocation-free per harness rules)
__device__ float g_deg[NMAX];
__device__ float g_dinv[NMAX];
__device__ int   g_rowptr[NMAX];   // CSR start offsets (by dst)
__device__ int   g_cursor[NMAX];   // fill cursors; after fill == row end
__device__ int   g_csr[EMAX];      // src indices grouped by dst
__device__ int   g_bsum[NBLK];     // scan block sums
__device__ float g_xs[NMAX * 128]; // (x@W1) * dinv[row]
__device__ float g_agg1[NMAX * 128];
__device__ float g_hs[NMAX * 40];  // (h@W2) * dinv[row]

// ---------------------------------------------------------------------------
// degree
// ---------------------------------------------------------------------------
__global__ void k_deg_init(int n) {
    int i = blockIdx.x * blockDim.x + threadIdx.x;
    if (i < n) g_deg[i] = 1.0f;  // self-loop contributes 1
}

__global__ void k_deg_edges(const int* __restrict__ ei, int E) {
    int e = blockIdx.x * blockDim.x + threadIdx.x;
    if (e < E) atomicAdd(&g_deg[ei[E + e]], 1.0f);
}

__global__ void k_dinv(int n) {
    int i = blockIdx.x * blockDim.x + threadIdx.x;
    if (i < n) g_dinv[i] = rsqrtf(g_deg[i]);
}

// ---------------------------------------------------------------------------
// CSR build: exclusive scan of per-dst edge counts (= deg - 1), then fill
// ---------------------------------------------------------------------------
__global__ void k_scan_block(int n) {
    __shared__ int s[NBLK];
    int i = blockIdx.x * NBLK + threadIdx.x;
    int v = (i < n) ? (int)g_deg[i] - 1 : 0;
    s[threadIdx.x] = v;
    __syncthreads();
#pragma unroll
    for (int off = 1; off < NBLK; off <<= 1) {
        int t = (threadIdx.x >= off) ? s[threadIdx.x - off] : 0;
        __syncthreads();
        s[threadIdx.x] += t;
        __syncthreads();
    }
    if (i < n) g_rowptr[i] = s[threadIdx.x] - v;  // block-local exclusive
    if (threadIdx.x == NBLK - 1) g_bsum[blockIdx.x] = s[NBLK - 1];
}

__global__ void k_scan_top(int nb) {
    __shared__ int s[NBLK];
    int v = (threadIdx.x < nb) ? g_bsum[threadIdx.x] : 0;
    s[threadIdx.x] = v;
    __syncthreads();
#pragma unroll
    for (int off = 1; off < NBLK; off <<= 1) {
        int t = (threadIdx.x >= off) ? s[threadIdx.x - off] : 0;
        __syncthreads();
        s[threadIdx.x] += t;
        __syncthreads();
    }
    g_bsum[threadIdx.x] = s[threadIdx.x] - v;  // exclusive block offsets
}

__global__ void k_scan_add(int n) {
    int i = blockIdx.x * NBLK + threadIdx.x;
    if (i < n) {
        int st = g_rowptr[i] + g_bsum[blockIdx.x];
        g_rowptr[i] = st;
        g_cursor[i] = st;
    }
}

__global__ void k_fill(const int* __restrict__ ei, int E) {
    int e = blockIdx.x * blockDim.x + threadIdx.x;
    if (e >= E) return;
    int dst = ei[E + e];
    int pos = atomicAdd(&g_cursor[dst], 1);
    g_csr[pos] = ei[e];
}

// ---------------------------------------------------------------------------
// GEMM1: xs = (x @ W1) * dinv[row]    [N,128] @ [128,128]
// 256 threads, 64 rows x 128 cols, two K=64 smem tiles (48KB static).
// ---------------------------------------------------------------------------
__global__ void k_gemm1(const float* __restrict__ x, const float* __restrict__ W,
                        int nrows) {
    __shared__ float4 sW[64 * 32];  // 64 k-rows x 128 cols  (32KB)
    __shared__ float4 sX[64 * 16];  // 64 rows  x 64 cols    (16KB)
    int tid = threadIdx.x;
    int rowBase = blockIdx.x * 64;
    int cg = tid & 31;
    int rg = tid >> 5;

    float4 acc[8];
#pragma unroll
    for (int r = 0; r < 8; r++) acc[r] = make_float4(0.f, 0.f, 0.f, 0.f);

    const float4* X4 = (const float4*)x;
    const float4* W4 = (const float4*)W;

    for (int kt = 0; kt < 2; kt++) {
        __syncthreads();
        for (int i = tid; i < 64 * 32; i += 256) {
            int kr = i >> 5, c = i & 31;
            sW[i] = W4[(kt * 64 + kr) * 32 + c];
        }
        for (int i = tid; i < 64 * 16; i += 256) {
            int r = i >> 4, c = i & 15;
            int grow = rowBase + r;
            sX[i] = (grow < nrows) ? X4[grow * 32 + kt * 16 + c]
                                   : make_float4(0.f, 0.f, 0.f, 0.f);
        }
        __syncthreads();
#pragma unroll
        for (int k4 = 0; k4 < 16; k4++) {
            float4 w0 = sW[(k4 * 4 + 0) * 32 + cg];
            float4 w1 = sW[(k4 * 4 + 1) * 32 + cg];
            float4 w2 = sW[(k4 * 4 + 2) * 32 + cg];
            float4 w3 = sW[(k4 * 4 + 3) * 32 + cg];
#pragma unroll
            for (int r = 0; r < 8; r++) {
                float4 xv = sX[(rg * 8 + r) * 16 + k4];
                acc[r].x += xv.x * w0.x + xv.y * w1.x + xv.z * w2.x + xv.w * w3.x;
                acc[r].y += xv.x * w0.y + xv.y * w1.y + xv.z * w2.y + xv.w * w3.y;
                acc[r].z += xv.x * w0.z + xv.y * w1.z + xv.z * w2.z + xv.w * w3.z;
                acc[r].w += xv.x * w0.w + xv.y * w1.w + xv.z * w2.w + xv.w * w3.w;
            }
        }
    }
    float4* xs4 = (float4*)g_xs;
#pragma unroll
    for (int r = 0; r < 8; r++) {
        int grow = rowBase + rg * 8 + r;
        if (grow < nrows) {
            float d = g_dinv[grow];
            xs4[grow * 32 + cg] =
                make_float4(acc[r].x * d, acc[r].y * d, acc[r].z * d, acc[r].w * d);
        }
    }
}

// ---------------------------------------------------------------------------
// Aggregation layer 1 (atomic-free): agg1[node] = xs[node] + sum xs[csr[...]]
// One warp per node: lane = float4 chunk (32 x 16B = 512B row).
// ---------------------------------------------------------------------------
__global__ void k_agg1(int n) {
    int t = blockIdx.x * blockDim.x + threadIdx.x;
    int node = t >> 5;
    if (node >= n) return;
    int ch = t & 31;
    const float4* xs4 = (const float4*)g_xs;
    float4 acc = xs4[node * 32 + ch];  // self-loop term
    int e = g_rowptr[node];
    int end = g_cursor[node];
    for (; e + 1 < end; e += 2) {   // 2-way ILP on the gather
        int s0 = g_csr[e];
        int s1 = g_csr[e + 1];
        float4 v0 = xs4[s0 * 32 + ch];
        float4 v1 = xs4[s1 * 32 + ch];
        acc.x += v0.x + v1.x;
        acc.y += v0.y + v1.y;
        acc.z += v0.z + v1.z;
        acc.w += v0.w + v1.w;
    }
    if (e < end) {
        float4 v = xs4[g_csr[e] * 32 + ch];
        acc.x += v.x; acc.y += v.y; acc.z += v.z; acc.w += v.w;
    }
    ((float4*)g_agg1)[node * 32 + ch] = acc;
}

// ---------------------------------------------------------------------------
// GEMM2: hs = (relu(dinv[row]*agg1 + b1) @ W2) * dinv[row]   [N,128]@[128,40]
// ---------------------------------------------------------------------------
__global__ void k_gemm2(const float* __restrict__ b1, const float* __restrict__ W2,
                        int nrows) {
    __shared__ float2 sW[128 * 20];  // 20KB
    __shared__ float sH[48 * 128];   // 24KB
    int tid = threadIdx.x;
    int rowBase = blockIdx.x * 48;

    const float2* W2v = (const float2*)W2;
    for (int i = tid; i < 128 * 20; i += 256) sW[i] = W2v[i];

    const float4* A4 = (const float4*)g_agg1;
    const float4* B14 = (const float4*)b1;
    float4* sH4 = (float4*)sH;
    for (int i = tid; i < 48 * 32; i += 256) {
        int r = i >> 5, c = i & 31;
        int grow = rowBase + r;
        float4 v = (grow < nrows) ? A4[grow * 32 + c] : make_float4(0.f, 0.f, 0.f, 0.f);
        float d = (grow < nrows) ? g_dinv[grow] : 0.f;
        float4 b = B14[c];
        v.x = fmaxf(v.x * d + b.x, 0.f);
        v.y = fmaxf(v.y * d + b.y, 0.f);
        v.z = fmaxf(v.z * d + b.z, 0.f);
        v.w = fmaxf(v.w * d + b.w, 0.f);
        sH4[i] = v;
    }
    __syncthreads();

    int w = tid >> 5, lane = tid & 31;
    bool act = lane < 20;
    float2 acc[6];
#pragma unroll
    for (int r = 0; r < 6; r++) acc[r] = make_float2(0.f, 0.f);

#pragma unroll 4
    for (int k = 0; k < 128; k++) {
        float2 wv = act ? sW[k * 20 + lane] : make_float2(0.f, 0.f);
#pragma unroll
        for (int r = 0; r < 6; r++) {
            float hv = sH[(w * 6 + r) * 128 + k];
            acc[r].x += hv * wv.x;
            acc[r].y += hv * wv.y;
        }
    }

    if (act) {
        float2* hs2 = (float2*)g_hs;
#pragma unroll
        for (int r = 0; r < 6; r++) {
            int grow = rowBase + w * 6 + r;
            if (grow < nrows) {
                float d = g_dinv[grow];
                hs2[grow * 20 + lane] = make_float2(acc[r].x * d, acc[r].y * d);
            }
        }
    }
}

// ---------------------------------------------------------------------------
// Aggregation layer 2 + epilogue: out = dinv[node]*(hs[node]+sum hs[src]) + b2
// One thread per (node, float4 chunk); 10 chunks per node.
// ---------------------------------------------------------------------------
__global__ void k_agg2(const float* __restrict__ b2, float* __restrict__ out, int n) {
    int t = blockIdx.x * blockDim.x + threadIdx.x;
    if (t >= n * 10) return;
    int node = t / 10;
    int j = t - node * 10;
    const float4* hs4 = (const float4*)g_hs;
    float4 acc = hs4[node * 10 + j];  // self-loop term
    int e = g_rowptr[node];
    int end = g_cursor[node];
    for (; e + 1 < end; e += 2) {
        int s0 = g_csr[e];
        int s1 = g_csr[e + 1];
        float4 v0 = hs4[s0 * 10 + j];
        float4 v1 = hs4[s1 * 10 + j];
        acc.x += v0.x + v1.x;
        acc.y += v0.y + v1.y;
        acc.z += v0.z + v1.z;
        acc.w += v0.w + v1.w;
    }
    if (e < end) {
        float4 v = hs4[g_csr[e] * 10 + j];
        acc.x += v.x; acc.y += v.y; acc.z += v.z; acc.w += v.w;
    }
    float d = g_dinv[node];
    float4 b = ((const float4*)b2)[j];
    ((float4*)out)[t] = make_float4(acc.x * d + b.x, acc.y * d + b.y,
                                    acc.z * d + b.z, acc.w * d + b.w);
}

// ---------------------------------------------------------------------------
extern "C" void kernel_launch(void* const* d_in, const int* in_sizes, int n_in,
                              void* d_out, int out_size) {
    const float* x = (const float*)d_in[0];
    const int* ei = (const int*)d_in[1];   // int32 (jax x64 disabled)
    const float* W1 = (const float*)d_in[2];
    const float* b1 = (const float*)d_in[3];
    const float* W2 = (const float*)d_in[4];
    const float* b2 = (const float*)d_in[5];
    float* out = (float*)d_out;

    int N = in_sizes[0] / 128;  // 50000
    int E = in_sizes[1] / 2;    // 640000
    int nb = (N + NBLK - 1) / NBLK;

    k_deg_init<<<nb, NBLK>>>(N);
    k_deg_edges<<<(E + 255) / 256, 256>>>(ei, E);
    k_dinv<<<nb, NBLK>>>(N);

    k_scan_block<<<nb, NBLK>>>(N);
    k_scan_top<<<1, NBLK>>>(nb);
    k_scan_add<<<nb, NBLK>>>(N);
    k_fill<<<(E + 255) / 256, 256>>>(ei, E);

    k_gemm1<<<(N + 63) / 64, 256>>>(x, W1, N);
    k_agg1<<<(N * 32 + 255) / 256, 256>>>(N);

    k_gemm2<<<(N + 47) / 48, 256>>>(b1, W2, N);
    k_agg2<<<(N * 10 + 255) / 256, 256>>>(b2, out, N);
}